// round 3
// baseline (speedup 1.0000x reference)
#include <cuda_runtime.h>
#include <math.h>

#define EPSF 1.1920929e-07f

// ---------------- scratch (__device__ globals; no allocations) ----------------
__device__ float d_logits[4096];                 // (8,512)
__device__ int   d_topk[32];                     // (8,4) sorted ascending
__device__ float d_qkvg[8 * 64 * 4096];          // selected tokens' projections
__device__ float d_Qb[8 * 8 * 65 * 128];         // (b,h,s,c) rope+rms+tao q
__device__ float d_Kb[8 * 8 * 65 * 128];
__device__ float d_Vb[8 * 8 * 65 * 128];
__device__ float d_yg[8 * 64 * 1024];            // gated attention output
__device__ float d_part[8 * 512 * 128];          // split-K partials for out GEMM

// ---------------- K1: per-patch score logit ----------------
// logit[b,p] = (xp . patch_w) * rsqrt(mean(xp^2)+eps)   (softmax is monotone ->
// top-k over logits == top-k over softmax scores)
__global__ __launch_bounds__(256) void k_score(const float* __restrict__ x,
                                               const float* __restrict__ pw) {
    int pid = blockIdx.x;                        // b*512 + p
    const float4* xv = (const float4*)(x + (size_t)pid * 2048);
    const float4* pv = (const float4*)pw;
    int tid = threadIdx.x;
    float ss = 0.f, dp = 0.f;
#pragma unroll
    for (int j = 0; j < 2; j++) {
        float4 v = xv[tid + j * 256];
        float4 w = pv[tid + j * 256];
        ss += v.x * v.x + v.y * v.y + v.z * v.z + v.w * v.w;
        dp += v.x * w.x + v.y * w.y + v.z * w.z + v.w * w.w;
    }
#pragma unroll
    for (int o = 16; o; o >>= 1) {
        ss += __shfl_xor_sync(0xffffffffu, ss, o);
        dp += __shfl_xor_sync(0xffffffffu, dp, o);
    }
    __shared__ float sss[8], sdp[8];
    int w = tid >> 5;
    if ((tid & 31) == 0) { sss[w] = ss; sdp[w] = dp; }
    __syncthreads();
    if (tid == 0) {
        float S = 0.f, D = 0.f;
#pragma unroll
        for (int i = 0; i < 8; i++) { S += sss[i]; D += sdp[i]; }
        d_logits[pid] = D * rsqrtf(S * (1.0f / 2048.0f) + EPSF);
    }
}

// ---------------- K2: top-4 indices per batch, sorted ascending ----------------
__global__ __launch_bounds__(512) void k_topk() {
    int b = blockIdx.x;
    int tid = threadIdx.x;
    __shared__ float vals[512];
    __shared__ float rv[512];
    __shared__ int ri[512];
    __shared__ int win[4];
    vals[tid] = d_logits[b * 512 + tid];
    __syncthreads();
    for (int r = 0; r < 4; r++) {
        rv[tid] = vals[tid]; ri[tid] = tid;
        __syncthreads();
        for (int s = 256; s > 0; s >>= 1) {
            if (tid < s) {
                float ov = rv[tid + s]; int oi = ri[tid + s];
                if (ov > rv[tid] || (ov == rv[tid] && oi < ri[tid])) {
                    rv[tid] = ov; ri[tid] = oi;
                }
            }
            __syncthreads();
        }
        if (tid == 0) { win[r] = ri[0]; vals[ri[0]] = -1e30f; }
        __syncthreads();
    }
    if (tid == 0) {
        int a[4] = {win[0], win[1], win[2], win[3]};
        for (int i = 0; i < 4; i++)
            for (int j = i + 1; j < 4; j++)
                if (a[j] < a[i]) { int t = a[i]; a[i] = a[j]; a[j] = t; }
        for (int i = 0; i < 4; i++) d_topk[b * 4 + i] = a[i];
    }
}

// ---------------- K3: qkvg GEMM for the 64 selected tokens per batch ----------------
// grid (32 n-tiles, 8 batches), 256 threads; tile M=64 x N=128, K=128 (chunks of 32)
__global__ __launch_bounds__(256) void k_qkvg(const float* __restrict__ x,
                                              const float* __restrict__ W) {
    int nt = blockIdx.x, b = blockIdx.y;
    int tid = threadIdx.x;
    __shared__ __align__(16) float Xs[32][68];    // [k][m]
    __shared__ __align__(16) float Ws[32][132];   // [k][n]
    __shared__ int toks[64];
    if (tid < 64) {
        int p = tid >> 4;
        toks[tid] = d_topk[b * 4 + p] * 16 + (tid & 15);
    }
    __syncthreads();
    int tx = tid & 15, ty = tid >> 4;
    int m0 = ty * 4, n0 = tx * 8;
    float acc[4][8];
#pragma unroll
    for (int i = 0; i < 4; i++)
#pragma unroll
        for (int j = 0; j < 8; j++) acc[i][j] = 0.f;

#pragma unroll 1
    for (int kc = 0; kc < 4; kc++) {
#pragma unroll
        for (int jj = 0; jj < 2; jj++) {
            int idx = tid + jj * 256;
            int m = idx >> 3, kq = idx & 7;
            float4 v = *(const float4*)(x + ((size_t)(b * 8192 + toks[m])) * 128 + kc * 32 + kq * 4);
            Xs[kq * 4 + 0][m] = v.x; Xs[kq * 4 + 1][m] = v.y;
            Xs[kq * 4 + 2][m] = v.z; Xs[kq * 4 + 3][m] = v.w;
        }
#pragma unroll
        for (int jj = 0; jj < 4; jj++) {
            int idx = tid + jj * 256;
            int c = idx >> 3, kq = idx & 7;
            float4 v = *(const float4*)(W + ((size_t)(nt * 128 + c)) * 128 + kc * 32 + kq * 4);
            Ws[kq * 4 + 0][c] = v.x; Ws[kq * 4 + 1][c] = v.y;
            Ws[kq * 4 + 2][c] = v.z; Ws[kq * 4 + 3][c] = v.w;
        }
        __syncthreads();
#pragma unroll
        for (int k = 0; k < 32; k++) {
            float4 xv = *(const float4*)&Xs[k][m0];
            float4 wa = *(const float4*)&Ws[k][n0];
            float4 wb = *(const float4*)&Ws[k][n0 + 4];
            float xr[4] = {xv.x, xv.y, xv.z, xv.w};
            float wr[8] = {wa.x, wa.y, wa.z, wa.w, wb.x, wb.y, wb.z, wb.w};
#pragma unroll
            for (int i = 0; i < 4; i++)
#pragma unroll
                for (int j = 0; j < 8; j++) acc[i][j] += xr[i] * wr[j];
        }
        __syncthreads();
    }
#pragma unroll
    for (int i = 0; i < 4; i++) {
        float* dst = d_qkvg + ((size_t)(b * 64 + m0 + i)) * 4096 + nt * 128 + n0;
        *(float4*)dst = make_float4(acc[i][0], acc[i][1], acc[i][2], acc[i][3]);
        *(float4*)(dst + 4) = make_float4(acc[i][4], acc[i][5], acc[i][6], acc[i][7]);
    }
}

// ---------------- K4: build Q/K/V with sink + rope + rmsnorm + tao ----------------
// grid (65 s, 8 h, 8 b), 128 threads (one per channel)
__global__ __launch_bounds__(128) void k_ropenorm(const float* __restrict__ cosb,
                                                  const float* __restrict__ sinb,
                                                  const float* __restrict__ sink,
                                                  const float* __restrict__ tao) {
    int s = blockIdx.x, h = blockIdx.y, b = blockIdx.z;
    int cc = threadIdx.x;
    __shared__ float sq[128], sk[128];
    __shared__ float red[8];
    float qv, kv, vv;
    if (s == 0) {
        float v = sink[h * 128 + cc];
        qv = kv = vv = v;
    } else {
        int s0 = s - 1;
        int p = s0 >> 4, r = s0 & 15;
        int cidx = (r & 3) * 1024 + h * 128 + cc;
        int tq = p * 16 + (r >> 2);                  // q uses tokens 0..3 of patch
        const float* base = d_qkvg + ((size_t)b * 64) * 4096;
        qv = base[(size_t)tq * 4096 + cidx];
        kv = base[(size_t)(tq + 4) * 4096 + cidx];   // k: tokens 4..7
        vv = base[(size_t)(tq + 8) * 4096 + cidx];   // v: tokens 8..11
    }
    sq[cc] = qv; sk[cc] = kv;
    __syncthreads();
    int d = cc & 63;
    float c_ = cosb[s * 64 + d], s_ = sinb[s * 64 + d];
    float rq, rk;
    if (cc < 64) {
        rq = sq[cc] * c_ + sq[cc + 64] * s_;
        rk = sk[cc] * c_ + sk[cc + 64] * s_;
    } else {
        rq = -sq[cc - 64] * s_ + sq[cc] * c_;
        rk = -sk[cc - 64] * s_ + sk[cc] * c_;
    }
    float a = rq * rq, bb = rk * rk;
#pragma unroll
    for (int o = 16; o; o >>= 1) {
        a += __shfl_xor_sync(0xffffffffu, a, o);
        bb += __shfl_xor_sync(0xffffffffu, bb, o);
    }
    int w = cc >> 5;
    if ((cc & 31) == 0) { red[w] = a; red[4 + w] = bb; }
    __syncthreads();
    float sumq = red[0] + red[1] + red[2] + red[3];
    float sumk = red[4] + red[5] + red[6] + red[7];
    float oq = rq * rsqrtf(sumq * (1.f / 128.f) + EPSF) * tao[0];
    float ok = rk * rsqrtf(sumk * (1.f / 128.f) + EPSF) * tao[1];
    size_t off = ((size_t)((b * 8 + h) * 65 + s)) * 128 + cc;
    d_Qb[off] = oq; d_Kb[off] = ok; d_Vb[off] = vv;
}

// ---------------- K5: causal attention per (b,h), S=65, + sigmoid gate ----------------
__global__ __launch_bounds__(256) void k_attn() {
    __shared__ __align__(16) float Ps[64 * 68];   // probs rows s=1..64
    __shared__ __align__(16) float Qc[32 * 68];   // [k][r] chunk
    __shared__ __align__(16) float Kc[32 * 132];  // [k][t] chunk (reused as V [t][k])
    int bh = blockIdx.x;
    int b = bh >> 3, h = bh & 7;
    int tid = threadIdx.x;
    int tx = tid & 15, ty = tid >> 4;
    const float* Qg = d_Qb + (size_t)bh * 65 * 128;
    const float* Kg = d_Kb + (size_t)bh * 65 * 128;
    const float* Vg = d_Vb + (size_t)bh * 65 * 128;
    int r0 = ty * 4, t0 = tx * 4;
    float acc[4][4];
#pragma unroll
    for (int i = 0; i < 4; i++)
#pragma unroll
        for (int j = 0; j < 4; j++) acc[i][j] = 0.f;

#pragma unroll 1
    for (int kc = 0; kc < 4; kc++) {
#pragma unroll
        for (int jj = 0; jj < 2; jj++) {
            int idx = tid + jj * 256;
            int r = idx >> 3, kq = idx & 7;
            float4 v = *(const float4*)(Qg + (size_t)(r + 1) * 128 + kc * 32 + kq * 4);
            Qc[(kq * 4 + 0) * 68 + r] = v.x; Qc[(kq * 4 + 1) * 68 + r] = v.y;
            Qc[(kq * 4 + 2) * 68 + r] = v.z; Qc[(kq * 4 + 3) * 68 + r] = v.w;
            float4 u = *(const float4*)(Kg + (size_t)r * 128 + kc * 32 + kq * 4);
            Kc[(kq * 4 + 0) * 68 + r] = u.x; Kc[(kq * 4 + 1) * 68 + r] = u.y;
            Kc[(kq * 4 + 2) * 68 + r] = u.z; Kc[(kq * 4 + 3) * 68 + r] = u.w;
        }
        __syncthreads();
#pragma unroll
        for (int k = 0; k < 32; k++) {
            float4 qv = *(const float4*)&Qc[k * 68 + r0];
            float4 kv = *(const float4*)&Kc[k * 68 + t0];
            float qr[4] = {qv.x, qv.y, qv.z, qv.w};
            float kr[4] = {kv.x, kv.y, kv.z, kv.w};
#pragma unroll
            for (int i = 0; i < 4; i++)
#pragma unroll
                for (int j = 0; j < 4; j++) acc[i][j] += qr[i] * kr[j];
        }
        __syncthreads();
    }
    const float scl = 0.08838834764831845f;  // 1/sqrt(128)
#pragma unroll
    for (int i = 0; i < 4; i++)
#pragma unroll
        for (int j = 0; j < 4; j++)
            Ps[(r0 + i) * 68 + t0 + j] = acc[i][j] * scl;
    if (tid == 0) {  // the single (s=64, t=64) element
        float dsum = 0.f;
        for (int k = 0; k < 128; k++) dsum += Qg[64 * 128 + k] * Kg[64 * 128 + k];
        Ps[63 * 68 + 64] = dsum * scl;
    }
    __syncthreads();
    if (tid < 64) {  // causal softmax of row r (s=r+1) over t<=s
        int r = tid, s = r + 1;
        float m = -1e30f;
        for (int t = 0; t <= s; t++) m = fmaxf(m, Ps[r * 68 + t]);
        float sum = 0.f;
        for (int t = 0; t <= s; t++) { float e = __expf(Ps[r * 68 + t] - m); Ps[r * 68 + t] = e; sum += e; }
        float inv = 1.f / sum;
        for (int t = 0; t <= s; t++) Ps[r * 68 + t] *= inv;
        for (int t = s + 1; t < 65; t++) Ps[r * 68 + t] = 0.f;
    }
    __syncthreads();
    // phase 3: Y = P @ V  (V streamed in 32-row chunks through Kc)
    int c0 = tx * 8;
    float y[4][8];
#pragma unroll
    for (int i = 0; i < 4; i++)
#pragma unroll
        for (int j = 0; j < 8; j++) y[i][j] = 0.f;
    float* Vc = Kc;  // [tt][k] stride 132
#pragma unroll 1
    for (int tc = 0; tc < 3; tc++) {
        int tbase = tc * 32;
        int tcnt = (tbase + 32 <= 65) ? 32 : (65 - tbase);
        for (int idx = tid; idx < tcnt * 32; idx += 256) {
            int tt = idx >> 5, kq = idx & 31;
            *(float4*)&Vc[tt * 132 + kq * 4] =
                *(const float4*)(Vg + (size_t)(tbase + tt) * 128 + kq * 4);
        }
        __syncthreads();
        for (int tt = 0; tt < tcnt; tt++) {
            int t = tbase + tt;
            float p0 = Ps[(r0 + 0) * 68 + t], p1 = Ps[(r0 + 1) * 68 + t];
            float p2 = Ps[(r0 + 2) * 68 + t], p3 = Ps[(r0 + 3) * 68 + t];
            float4 va = *(const float4*)&Vc[tt * 132 + c0];
            float4 vb = *(const float4*)&Vc[tt * 132 + c0 + 4];
            float vr[8] = {va.x, va.y, va.z, va.w, vb.x, vb.y, vb.z, vb.w};
#pragma unroll
            for (int j = 0; j < 8; j++) {
                y[0][j] += p0 * vr[j]; y[1][j] += p1 * vr[j];
                y[2][j] += p2 * vr[j]; y[3][j] += p3 * vr[j];
            }
        }
        __syncthreads();
    }
    // gate with sigmoid(g) (g: tokens 12..15 of each patch) and store
#pragma unroll
    for (int i = 0; i < 4; i++) {
        int r = r0 + i;
        int p = r >> 4, rr = r & 15;
        const float* gb = d_qkvg + ((size_t)(b * 64 + p * 16 + 12 + (rr >> 2))) * 4096
                          + (rr & 3) * 1024 + h * 128 + c0;
        float* og = d_yg + ((size_t)(b * 64 + r)) * 1024 + h * 128 + c0;
#pragma unroll
        for (int j = 0; j < 8; j++) {
            float g = gb[j];
            float sg = 1.f / (1.f + __expf(-g));
            og[j] = y[i][j] * sg;
        }
    }
}

// ---------------- K6: output GEMM, split-K=8, partials ----------------
// out(512x128) = yg(512x1024) @ W_out^T(128x1024); grid (8 mt, 2 nt, 8 kc)
__global__ __launch_bounds__(256) void k_out(const float* __restrict__ Wout) {
    int mt = blockIdx.x, nt = blockIdx.y, kc = blockIdx.z;
    __shared__ __align__(16) float Ys[32][68];
    __shared__ __align__(16) float Ws[32][68];
    int tid = threadIdx.x, tx = tid & 15, ty = tid >> 4;
    int m0 = ty * 4, n0 = tx * 4;
    float acc[4][4];
#pragma unroll
    for (int i = 0; i < 4; i++)
#pragma unroll
        for (int j = 0; j < 4; j++) acc[i][j] = 0.f;

#pragma unroll 1
    for (int ck = 0; ck < 4; ck++) {
        int kbase = kc * 128 + ck * 32;
#pragma unroll
        for (int jj = 0; jj < 2; jj++) {
            int idx = tid + jj * 256;
            int m = idx >> 3, kq = idx & 7;
            float4 v = *(const float4*)(d_yg + (size_t)(mt * 64 + m) * 1024 + kbase + kq * 4);
            Ys[kq * 4 + 0][m] = v.x; Ys[kq * 4 + 1][m] = v.y;
            Ys[kq * 4 + 2][m] = v.z; Ys[kq * 4 + 3][m] = v.w;
            float4 w = *(const float4*)(Wout + (size_t)(nt * 64 + m) * 1024 + kbase + kq * 4);
            Ws[kq * 4 + 0][m] = w.x; Ws[kq * 4 + 1][m] = w.y;
            Ws[kq * 4 + 2][m] = w.z; Ws[kq * 4 + 3][m] = w.w;
        }
        __syncthreads();
#pragma unroll
        for (int k = 0; k < 32; k++) {
            float4 yv = *(const float4*)&Ys[k][m0];
            float4 wv = *(const float4*)&Ws[k][n0];
            float yr[4] = {yv.x, yv.y, yv.z, yv.w};
            float wr[4] = {wv.x, wv.y, wv.z, wv.w};
#pragma unroll
            for (int i = 0; i < 4; i++)
#pragma unroll
                for (int j = 0; j < 4; j++) acc[i][j] += yr[i] * wr[j];
        }
        __syncthreads();
    }
#pragma unroll
    for (int i = 0; i < 4; i++) {
        float* dst = d_part + (size_t)(kc * 512 + mt * 64 + m0 + i) * 128 + nt * 64 + n0;
        *(float4*)dst = make_float4(acc[i][0], acc[i][1], acc[i][2], acc[i][3]);
    }
}

// ---------------- K7: reduce split-K partials ----------------
__global__ __launch_bounds__(256) void k_reduce(float* __restrict__ out) {
    int i = blockIdx.x * 256 + threadIdx.x;  // 65536 outputs
    float s = 0.f;
#pragma unroll
    for (int kc = 0; kc < 8; kc++) s += d_part[kc * 65536 + i];
    out[i] = s;
}

// ---------------- launch ----------------
extern "C" void kernel_launch(void* const* d_in, const int* in_sizes, int n_in,
                              void* d_out, int out_size) {
    const float* x     = (const float*)d_in[0];
    const float* cosb  = (const float*)d_in[1];
    const float* sinb  = (const float*)d_in[2];
    const float* sink  = (const float*)d_in[3];
    const float* Wqkvg = (const float*)d_in[4];
    const float* pw    = (const float*)d_in[5];
    const float* Wout  = (const float*)d_in[6];
    const float* tao   = (const float*)d_in[7];
    float* out = (float*)d_out;

    k_score<<<4096, 256>>>(x, pw);
    k_topk<<<8, 512>>>();
    k_qkvg<<<dim3(32, 8), 256>>>(x, Wqkvg);
    k_ropenorm<<<dim3(65, 8, 8), 128>>>(cosb, sinb, sink, tao);
    k_attn<<<64, 256>>>();
    k_out<<<dim3(8, 2, 8), 256>>>(Wout);
    k_reduce<<<256, 256>>>(out);
}

// round 5
// speedup vs baseline: 1.0264x; 1.0264x over previous
#include <cuda_runtime.h>
#include <math.h>

#define EPSF 1.1920929e-07f
typedef unsigned long long ull;

// ---------------- f32x2 packed-FMA helpers (sm_103a) ----------------
__device__ __forceinline__ ull f2pk(float a, float b) {
    ull r; asm("mov.b64 %0, {%1,%2};" : "=l"(r) : "f"(a), "f"(b)); return r;
}
__device__ __forceinline__ ull ffma2(ull a, ull b, ull c) {
    ull d; asm("fma.rn.f32x2 %0, %1, %2, %3;" : "=l"(d) : "l"(a), "l"(b), "l"(c)); return d;
}
__device__ __forceinline__ float2 f2up(ull v) {
    float2 f; asm("mov.b64 {%0,%1}, %2;" : "=f"(f.x), "=f"(f.y) : "l"(v)); return f;
}

// ---------------- scratch (__device__ globals; no allocations) ----------------
__device__ float d_logits[4096];                 // (8,512)
__device__ int   d_topk[32];                     // (8,4) sorted ascending
__device__ float d_qkvg[8 * 64 * 4096];          // selected tokens' projections
__device__ float d_Qb[8 * 8 * 65 * 128];         // (b,h,s,c) rope+rms+tao q
__device__ float d_Kb[8 * 8 * 65 * 128];
__device__ float d_Vb[8 * 8 * 65 * 128];
__device__ float d_yg[8 * 64 * 1024];            // gated attention output

// ---------------- K1: per-patch score logit ----------------
__global__ __launch_bounds__(256) void k_score(const float* __restrict__ x,
                                               const float* __restrict__ pw) {
    int pid = blockIdx.x;                        // b*512 + p
    const float4* xv = (const float4*)(x + (size_t)pid * 2048);
    const float4* pv = (const float4*)pw;
    int tid = threadIdx.x;
    float ss = 0.f, dp = 0.f;
#pragma unroll
    for (int j = 0; j < 2; j++) {
        float4 v = xv[tid + j * 256];
        float4 w = pv[tid + j * 256];
        ss += v.x * v.x + v.y * v.y + v.z * v.z + v.w * v.w;
        dp += v.x * w.x + v.y * w.y + v.z * w.z + v.w * w.w;
    }
#pragma unroll
    for (int o = 16; o; o >>= 1) {
        ss += __shfl_xor_sync(0xffffffffu, ss, o);
        dp += __shfl_xor_sync(0xffffffffu, dp, o);
    }
    __shared__ float sss[8], sdp[8];
    int w = tid >> 5;
    if ((tid & 31) == 0) { sss[w] = ss; sdp[w] = dp; }
    __syncthreads();
    if (tid == 0) {
        float S = 0.f, D = 0.f;
#pragma unroll
        for (int i = 0; i < 8; i++) { S += sss[i]; D += sdp[i]; }
        d_logits[pid] = D * rsqrtf(S * (1.0f / 2048.0f) + EPSF);
    }
}

// ---------------- K2: top-4 per batch; one warp per batch, shfl-only ----------------
__global__ __launch_bounds__(256) void k_topk() {
    int wid = threadIdx.x >> 5, lane = threadIdx.x & 31;
    int b = wid;                                  // 8 warps = 8 batches
    float v[16];
#pragma unroll
    for (int i = 0; i < 16; i++) v[i] = d_logits[b * 512 + i * 32 + lane];
    int got[4];
#pragma unroll
    for (int r = 0; r < 4; r++) {
        float bv = -1e30f; int bi = 1 << 30;
#pragma unroll
        for (int i = 0; i < 16; i++) {
            int idx = i * 32 + lane;
            if (v[i] > bv || (v[i] == bv && idx < bi)) { bv = v[i]; bi = idx; }
        }
#pragma unroll
        for (int o = 16; o; o >>= 1) {
            float ov = __shfl_xor_sync(0xffffffffu, bv, o);
            int   oi = __shfl_xor_sync(0xffffffffu, bi, o);
            if (ov > bv || (ov == bv && oi < bi)) { bv = ov; bi = oi; }
        }
        got[r] = bi;
        if ((bi & 31) == lane) v[bi >> 5] = -1e30f;
    }
    if (lane == 0) {
#pragma unroll
        for (int i = 0; i < 4; i++)
#pragma unroll
            for (int j = 0; j < 3; j++)
                if (got[j + 1] < got[j]) { int t = got[j]; got[j] = got[j + 1]; got[j + 1] = t; }
#pragma unroll
        for (int i = 0; i < 4; i++) d_topk[b * 4 + i] = got[i];
    }
}

// ---------------- K3: qkvg GEMM for selected tokens (f32x2) ----------------
// grid (32 n-tiles, 8 batches), 256 threads; tile M=64 x N=128, K chunks of 32
__global__ __launch_bounds__(256) void k_qkvg(const float* __restrict__ x,
                                              const float* __restrict__ W) {
    int nt = blockIdx.x, b = blockIdx.y;
    int tid = threadIdx.x;
    __shared__ __align__(16) float Xs[32][68];    // [k][m]
    __shared__ __align__(16) float Ws[32][132];   // [k][n]
    __shared__ int toks[64];
    if (tid < 64) toks[tid] = d_topk[b * 4 + (tid >> 4)] * 16 + (tid & 15);
    __syncthreads();
    int tx = tid & 15, ty = tid >> 4;
    int m0 = ty * 4, n0 = tx * 8;
    ull acc[4][4];
#pragma unroll
    for (int i = 0; i < 4; i++)
#pragma unroll
        for (int j = 0; j < 4; j++) acc[i][j] = 0ull;

#pragma unroll 1
    for (int kc = 0; kc < 4; kc++) {
#pragma unroll
        for (int jj = 0; jj < 2; jj++) {
            int idx = tid + jj * 256;
            int m = idx >> 3, kq = idx & 7;
            float4 v = *(const float4*)(x + ((size_t)(b * 8192 + toks[m])) * 128 + kc * 32 + kq * 4);
            Xs[kq * 4 + 0][m] = v.x; Xs[kq * 4 + 1][m] = v.y;
            Xs[kq * 4 + 2][m] = v.z; Xs[kq * 4 + 3][m] = v.w;
        }
#pragma unroll
        for (int jj = 0; jj < 4; jj++) {
            int idx = tid + jj * 256;
            int c = idx >> 3, kq = idx & 7;
            float4 v = *(const float4*)(W + ((size_t)(nt * 128 + c)) * 128 + kc * 32 + kq * 4);
            Ws[kq * 4 + 0][c] = v.x; Ws[kq * 4 + 1][c] = v.y;
            Ws[kq * 4 + 2][c] = v.z; Ws[kq * 4 + 3][c] = v.w;
        }
        __syncthreads();
#pragma unroll
        for (int k = 0; k < 32; k++) {
            float4 xv = *(const float4*)&Xs[k][m0];
            ull xb0 = f2pk(xv.x, xv.x), xb1 = f2pk(xv.y, xv.y);
            ull xb2 = f2pk(xv.z, xv.z), xb3 = f2pk(xv.w, xv.w);
            const ull* wp = (const ull*)&Ws[k][n0];
            ull w0 = wp[0], w1 = wp[1], w2 = wp[2], w3 = wp[3];
            acc[0][0] = ffma2(xb0, w0, acc[0][0]); acc[0][1] = ffma2(xb0, w1, acc[0][1]);
            acc[0][2] = ffma2(xb0, w2, acc[0][2]); acc[0][3] = ffma2(xb0, w3, acc[0][3]);
            acc[1][0] = ffma2(xb1, w0, acc[1][0]); acc[1][1] = ffma2(xb1, w1, acc[1][1]);
            acc[1][2] = ffma2(xb1, w2, acc[1][2]); acc[1][3] = ffma2(xb1, w3, acc[1][3]);
            acc[2][0] = ffma2(xb2, w0, acc[2][0]); acc[2][1] = ffma2(xb2, w1, acc[2][1]);
            acc[2][2] = ffma2(xb2, w2, acc[2][2]); acc[2][3] = ffma2(xb2, w3, acc[2][3]);
            acc[3][0] = ffma2(xb3, w0, acc[3][0]); acc[3][1] = ffma2(xb3, w1, acc[3][1]);
            acc[3][2] = ffma2(xb3, w2, acc[3][2]); acc[3][3] = ffma2(xb3, w3, acc[3][3]);
        }
        __syncthreads();
    }
#pragma unroll
    for (int i = 0; i < 4; i++) {
        float2 a = f2up(acc[i][0]), bq = f2up(acc[i][1]);
        float2 c = f2up(acc[i][2]), d = f2up(acc[i][3]);
        float* dst = d_qkvg + ((size_t)(b * 64 + m0 + i)) * 4096 + nt * 128 + n0;
        *(float4*)dst       = make_float4(a.x, a.y, bq.x, bq.y);
        *(float4*)(dst + 4) = make_float4(c.x, c.y, d.x, d.y);
    }
}

// ---------------- K4: sink + rope + rmsnorm + tao; warp-per-row ----------------
// grid 64 (b*8+h), 256 threads (8 warps); warp handles rows s = wid, wid+8, ...
__global__ __launch_bounds__(256) void k_ropenorm(const float* __restrict__ cosb,
                                                  const float* __restrict__ sinb,
                                                  const float* __restrict__ sink,
                                                  const float* __restrict__ tao) {
    int bh = blockIdx.x;
    int b = bh >> 3, h = bh & 7;
    int wid = threadIdx.x >> 5, lane = threadIdx.x & 31;
    float t0 = tao[0], t1 = tao[1];
    int c0 = lane * 4;
    int d0 = c0 & 63;
    float sg = (lane < 16) ? 1.f : -1.f;
    for (int s = wid; s < 65; s += 8) {
        float4 q, k, v;
        if (s == 0) {
            q = *(const float4*)(sink + h * 128 + c0); k = q; v = q;
        } else {
            int s0 = s - 1;
            int p = s0 >> 4, r = s0 & 15;
            int cidx = (r & 3) * 1024 + h * 128 + c0;
            int tq = p * 16 + (r >> 2);
            const float* base = d_qkvg + (size_t)b * 64 * 4096;
            q = *(const float4*)(base + (size_t)tq * 4096 + cidx);
            k = *(const float4*)(base + (size_t)(tq + 4) * 4096 + cidx);
            v = *(const float4*)(base + (size_t)(tq + 8) * 4096 + cidx);
        }
        float4 cv = *(const float4*)(cosb + s * 64 + d0);
        float4 sv = *(const float4*)(sinb + s * 64 + d0);
        float qox = __shfl_xor_sync(0xffffffffu, q.x, 16);
        float qoy = __shfl_xor_sync(0xffffffffu, q.y, 16);
        float qoz = __shfl_xor_sync(0xffffffffu, q.z, 16);
        float qow = __shfl_xor_sync(0xffffffffu, q.w, 16);
        float kox = __shfl_xor_sync(0xffffffffu, k.x, 16);
        float koy = __shfl_xor_sync(0xffffffffu, k.y, 16);
        float koz = __shfl_xor_sync(0xffffffffu, k.z, 16);
        float kow = __shfl_xor_sync(0xffffffffu, k.w, 16);
        float rqx = fmaf(q.x, cv.x, sg * qox * sv.x);
        float rqy = fmaf(q.y, cv.y, sg * qoy * sv.y);
        float rqz = fmaf(q.z, cv.z, sg * qoz * sv.z);
        float rqw = fmaf(q.w, cv.w, sg * qow * sv.w);
        float rkx = fmaf(k.x, cv.x, sg * kox * sv.x);
        float rky = fmaf(k.y, cv.y, sg * koy * sv.y);
        float rkz = fmaf(k.z, cv.z, sg * koz * sv.z);
        float rkw = fmaf(k.w, cv.w, sg * kow * sv.w);
        float ssq = rqx * rqx + rqy * rqy + rqz * rqz + rqw * rqw;
        float ssk = rkx * rkx + rky * rky + rkz * rkz + rkw * rkw;
#pragma unroll
        for (int o = 16; o; o >>= 1) {
            ssq += __shfl_xor_sync(0xffffffffu, ssq, o);
            ssk += __shfl_xor_sync(0xffffffffu, ssk, o);
        }
        float nq = rsqrtf(ssq * (1.f / 128.f) + EPSF) * t0;
        float nk = rsqrtf(ssk * (1.f / 128.f) + EPSF) * t1;
        size_t off = ((size_t)bh * 65 + s) * 128 + c0;
        *(float4*)(d_Qb + off) = make_float4(rqx * nq, rqy * nq, rqz * nq, rqw * nq);
        *(float4*)(d_Kb + off) = make_float4(rkx * nk, rky * nk, rkz * nk, rkw * nk);
        *(float4*)(d_Vb + off) = v;
    }
}

// ---------------- K5: causal attention, 2 row-chunks per (b,h), f32x2 ----------------
// grid (2 chunks, 64 bh), 256 threads. chunk c handles rows s = c*32+1 .. c*32+32.
__global__ __launch_bounds__(256) void k_attn() {
    __shared__ __align__(16) float Ps[32 * 68];
    __shared__ __align__(16) float Buf[4224];     // Qc(32x36) + Kc(32x68); reused as Vc(32x132)
    float* Qc = Buf;
    float* Kc = Buf + 1152;
    int chunk = blockIdx.x, bh = blockIdx.y;
    int b = bh >> 3, h = bh & 7;
    int tid = threadIdx.x;
    int wid = tid >> 5, lane = tid & 31;
    const float* Qg = d_Qb + (size_t)bh * 65 * 128;
    const float* Kg = d_Kb + (size_t)bh * 65 * 128;
    const float* Vg = d_Vb + (size_t)bh * 65 * 128;
    int text = chunk ? 65 : 33;                   // t extent needed
    int r0 = wid * 4;                             // 4 local rows per warp
    int t0 = lane * 2;                            // 2 t per lane (one pair)
    ull acc[2][2] = {0ull, 0ull, 0ull, 0ull};
    float e64 = 0.f;

#pragma unroll 1
    for (int kc = 0; kc < 4; kc++) {
        {   // Qc: exactly 32 rows x 8 float4 = 256 loads
            int r = tid >> 3, kq = tid & 7;
            float4 qv = *(const float4*)(Qg + (size_t)(chunk * 32 + r + 1) * 128 + kc * 32 + kq * 4);
            Qc[(kq * 4 + 0) * 36 + r] = qv.x; Qc[(kq * 4 + 1) * 36 + r] = qv.y;
            Qc[(kq * 4 + 2) * 36 + r] = qv.z; Qc[(kq * 4 + 3) * 36 + r] = qv.w;
        }
        for (int idx = tid; idx < text * 8; idx += 256) {
            int t = idx >> 3, kq = idx & 7;
            float4 kv = *(const float4*)(Kg + (size_t)t * 128 + kc * 32 + kq * 4);
            Kc[(kq * 4 + 0) * 68 + t] = kv.x; Kc[(kq * 4 + 1) * 68 + t] = kv.y;
            Kc[(kq * 4 + 2) * 68 + t] = kv.z; Kc[(kq * 4 + 3) * 68 + t] = kv.w;
        }
        __syncthreads();
#pragma unroll
        for (int k = 0; k < 32; k++) {
            const ull* qp = (const ull*)&Qc[k * 36 + r0];   // rows r0..r0+3 = 2 pairs
            ull q0 = qp[0], q1 = qp[1];
            float2 kv = *(const float2*)&Kc[k * 68 + t0];
            ull kb0 = f2pk(kv.x, kv.x), kb1 = f2pk(kv.y, kv.y);
            acc[0][0] = ffma2(q0, kb0, acc[0][0]); acc[0][1] = ffma2(q0, kb1, acc[0][1]);
            acc[1][0] = ffma2(q1, kb0, acc[1][0]); acc[1][1] = ffma2(q1, kb1, acc[1][1]);
        }
        if (chunk == 1 && tid == 0) {
#pragma unroll
            for (int k = 0; k < 32; k++) e64 += Qc[k * 36 + 31] * Kc[k * 68 + 64];
        }
        __syncthreads();
    }
    const float scl = 0.08838834764831845f;       // 1/sqrt(128)
#pragma unroll
    for (int p = 0; p < 2; p++)
#pragma unroll
        for (int j = 0; j < 2; j++) {
            float2 f = f2up(acc[p][j]);
            Ps[(r0 + 2 * p)     * 68 + t0 + j] = f.x * scl;
            Ps[(r0 + 2 * p + 1) * 68 + t0 + j] = f.y * scl;
        }
    if (chunk == 1 && tid == 0) Ps[31 * 68 + 64] = e64 * scl;
    __syncthreads();
    if (tid < 32) {                               // softmax of row s = chunk*32+tid+1
        int r = tid, s = chunk * 32 + r + 1;
        float m = -1e30f;
        for (int t = 0; t <= s; t++) m = fmaxf(m, Ps[r * 68 + t]);
        float sum = 0.f;
        for (int t = 0; t <= s; t++) { float e = __expf(Ps[r * 68 + t] - m); Ps[r * 68 + t] = e; sum += e; }
        float inv = 1.f / sum;
        for (int t = 0; t <= s; t++) Ps[r * 68 + t] *= inv;
        for (int t = s + 1; t < 65; t++) Ps[r * 68 + t] = 0.f;
    }
    __syncthreads();
    // PV: warp -> 4 rows, lane -> 4 channels (2 pairs); V streamed through Buf
    float* Vc = Buf;                              // [t][c] stride 132
    int c0 = lane * 4;
    ull y[4][2];
#pragma unroll
    for (int i = 0; i < 4; i++) { y[i][0] = 0ull; y[i][1] = 0ull; }
#pragma unroll 1
    for (int tc = 0; tc * 32 < text; tc++) {
        int tb = tc * 32;
        int tcnt = min(32, text - tb);
        for (int idx = tid; idx < tcnt * 32; idx += 256) {
            int tt = idx >> 5, kq = idx & 31;
            *(float4*)&Vc[tt * 132 + kq * 4] = *(const float4*)(Vg + (size_t)(tb + tt) * 128 + kq * 4);
        }
        __syncthreads();
        for (int tt = 0; tt < tcnt; tt++) {
            int t = tb + tt;
            float p0 = Ps[(r0 + 0) * 68 + t], p1 = Ps[(r0 + 1) * 68 + t];
            float p2 = Ps[(r0 + 2) * 68 + t], p3 = Ps[(r0 + 3) * 68 + t];
            ull pb0 = f2pk(p0, p0), pb1 = f2pk(p1, p1);
            ull pb2 = f2pk(p2, p2), pb3 = f2pk(p3, p3);
            const ull* vp = (const ull*)&Vc[tt * 132 + c0];
            ull v0 = vp[0], v1 = vp[1];
            y[0][0] = ffma2(pb0, v0, y[0][0]); y[0][1] = ffma2(pb0, v1, y[0][1]);
            y[1][0] = ffma2(pb1, v0, y[1][0]); y[1][1] = ffma2(pb1, v1, y[1][1]);
            y[2][0] = ffma2(pb2, v0, y[2][0]); y[2][1] = ffma2(pb2, v1, y[2][1]);
            y[3][0] = ffma2(pb3, v0, y[3][0]); y[3][1] = ffma2(pb3, v1, y[3][1]);
        }
        __syncthreads();
    }
    // gate with sigmoid(g) and store
#pragma unroll
    for (int i = 0; i < 4; i++) {
        int rg = chunk * 32 + r0 + i;
        int p = rg >> 4, rr = rg & 15;
        const float* gb = d_qkvg + ((size_t)(b * 64 + p * 16 + 12 + (rr >> 2))) * 4096
                          + (rr & 3) * 1024 + h * 128 + c0;
        float4 g4 = *(const float4*)gb;
        float2 a = f2up(y[i][0]), cpr = f2up(y[i][1]);
        float4 o;
        o.x = a.x   / (1.f + __expf(-g4.x));
        o.y = a.y   / (1.f + __expf(-g4.y));
        o.z = cpr.x / (1.f + __expf(-g4.z));
        o.w = cpr.y / (1.f + __expf(-g4.w));
        *(float4*)(d_yg + ((size_t)(b * 64 + rg)) * 1024 + h * 128 + c0) = o;
    }
}

// ---------------- K6: output GEMM, split-K=8, atomicAdd into out (f32x2) ----------------
// out(512x128) += yg(512x1024) @ W_out^T ; grid (8 mt, 2 nt, 8 kc), 128 threads
__global__ __launch_bounds__(128) void k_out(const float* __restrict__ Wout,
                                             float* __restrict__ out) {
    int mt = blockIdx.x, nt = blockIdx.y, kc = blockIdx.z;
    __shared__ __align__(16) float Ys[32][68];
    __shared__ __align__(16) float Ws[32][68];
    int tid = threadIdx.x;
    int tx = tid & 7, ty = tid >> 3;              // 16 ty x 8 tx
    int m0 = ty * 4, n0 = tx * 8;
    ull acc[4][4];
#pragma unroll
    for (int i = 0; i < 4; i++)
#pragma unroll
        for (int j = 0; j < 4; j++) acc[i][j] = 0ull;

#pragma unroll 1
    for (int ck = 0; ck < 4; ck++) {
        int kbase = kc * 128 + ck * 32;
#pragma unroll
        for (int jj = 0; jj < 4; jj++) {
            int idx = tid + jj * 128;
            int m = idx >> 3, kq = idx & 7;
            float4 v = *(const float4*)(d_yg + (size_t)(mt * 64 + m) * 1024 + kbase + kq * 4);
            Ys[kq * 4 + 0][m] = v.x; Ys[kq * 4 + 1][m] = v.y;
            Ys[kq * 4 + 2][m] = v.z; Ys[kq * 4 + 3][m] = v.w;
            float4 w = *(const float4*)(Wout + (size_t)(nt * 64 + m) * 1024 + kbase + kq * 4);
            Ws[kq * 4 + 0][m] = w.x; Ws[kq * 4 + 1][m] = w.y;
            Ws[kq * 4 + 2][m] = w.z; Ws[kq * 4 + 3][m] = w.w;
        }
        __syncthreads();
#pragma unroll
        for (int k = 0; k < 32; k++) {
            float4 yv = *(const float4*)&Ys[k][m0];
            ull yb0 = f2pk(yv.x, yv.x), yb1 = f2pk(yv.y, yv.y);
            ull yb2 = f2pk(yv.z, yv.z), yb3 = f2pk(yv.w, yv.w);
            const ull* wp = (const ull*)&Ws[k][n0];
            ull w0 = wp[0], w1 = wp[1], w2 = wp[2], w3 = wp[3];
            acc[0][0] = ffma2(yb0, w0, acc[0][0]); acc[0][1] = ffma2(yb0, w1, acc[0][1]);
            acc[0][2] = ffma2(yb0, w2, acc[0][2]); acc[0][3] = ffma2(yb0, w3, acc[0][3]);
            acc[1][0] = ffma2(yb1, w0, acc[1][0]); acc[1][1] = ffma2(yb1, w1, acc[1][1]);
            acc[1][2] = ffma2(yb1, w2, acc[1][2]); acc[1][3] = ffma2(yb1, w3, acc[1][3]);
            acc[2][0] = ffma2(yb2, w0, acc[2][0]); acc[2][1] = ffma2(yb2, w1, acc[2][1]);
            acc[2][2] = ffma2(yb2, w2, acc[2][2]); acc[2][3] = ffma2(yb2, w3, acc[2][3]);
            acc[3][0] = ffma2(yb3, w0, acc[3][0]); acc[3][1] = ffma2(yb3, w1, acc[3][1]);
            acc[3][2] = ffma2(yb3, w2, acc[3][2]); acc[3][3] = ffma2(yb3, w3, acc[3][3]);
        }
        __syncthreads();
    }
#pragma unroll
    for (int i = 0; i < 4; i++) {
        float* dst = out + (size_t)(mt * 64 + m0 + i) * 128 + nt * 64 + n0;
#pragma unroll
        for (int j = 0; j < 4; j++) {
            float2 f = f2up(acc[i][j]);
            atomicAdd(dst + 2 * j,     f.x);
            atomicAdd(dst + 2 * j + 1, f.y);
        }
    }
}

// ---------------- launch ----------------
extern "C" void kernel_launch(void* const* d_in, const int* in_sizes, int n_in,
                              void* d_out, int out_size) {
    const float* x     = (const float*)d_in[0];
    const float* cosb  = (const float*)d_in[1];
    const float* sinb  = (const float*)d_in[2];
    const float* sink  = (const float*)d_in[3];
    const float* Wqkvg = (const float*)d_in[4];
    const float* pw    = (const float*)d_in[5];
    const float* Wout  = (const float*)d_in[6];
    const float* tao   = (const float*)d_in[7];
    float* out = (float*)d_out;

    cudaMemsetAsync(out, 0, (size_t)out_size * sizeof(float));
    k_score<<<4096, 256>>>(x, pw);
    k_topk<<<1, 256>>>();
    k_qkvg<<<dim3(32, 8), 256>>>(x, Wqkvg);
    k_ropenorm<<<64, 256>>>(cosb, sinb, sink, tao);
    k_attn<<<dim3(2, 64), 256>>>();
    k_out<<<dim3(8, 2, 8), 128>>>(Wout, out);
}

// round 6
// speedup vs baseline: 1.1456x; 1.1161x over previous
#include <cuda_runtime.h>
#include <math.h>

#define EPSF 1.1920929e-07f
typedef unsigned long long ull;

// ---------------- f32x2 packed-FMA helpers (sm_103a) ----------------
__device__ __forceinline__ ull f2pk(float a, float b) {
    ull r; asm("mov.b64 %0, {%1,%2};" : "=l"(r) : "f"(a), "f"(b)); return r;
}
__device__ __forceinline__ ull ffma2(ull a, ull b, ull c) {
    ull d; asm("fma.rn.f32x2 %0, %1, %2, %3;" : "=l"(d) : "l"(a), "l"(b), "l"(c)); return d;
}
__device__ __forceinline__ float2 f2up(ull v) {
    float2 f; asm("mov.b64 {%0,%1}, %2;" : "=f"(f.x), "=f"(f.y) : "l"(v)); return f;
}

// ---------------- scratch (__device__ globals; no allocations) ----------------
__device__ float d_logits[4096];                 // (8,512)
__device__ int   d_topk[32];                     // (8,4) sorted ascending
__device__ float d_Qb[8 * 8 * 65 * 128];         // (b,h,s,c) rope+rms+tao q
__device__ float d_Kb[8 * 8 * 65 * 128];
__device__ float d_Vb[8 * 8 * 65 * 128];
__device__ float d_g[8 * 64 * 1024];             // gate logits (b, r, h, c)
__device__ float d_yg[8 * 64 * 1024];            // gated attention output

// ---------------- K1: per-patch score logit; one warp per patch ----------------
// logit[b,p] = (xp . patch_w) * rsqrt(mean(xp^2)+eps)  (softmax monotone -> same top-k)
__global__ __launch_bounds__(256) void k_score(const float* __restrict__ x,
                                               const float* __restrict__ pw) {
    int wid = threadIdx.x >> 5, lane = threadIdx.x & 31;
    int pid = blockIdx.x * 8 + wid;              // 512 blocks * 8 warps = 4096 patches
    const float4* xv = (const float4*)(x + (size_t)pid * 2048);
    const float4* pv = (const float4*)pw;
    float ss = 0.f, dp = 0.f;
#pragma unroll
    for (int i = 0; i < 16; i++) {
        float4 v = xv[i * 32 + lane];
        float4 w = pv[i * 32 + lane];
        ss += v.x * v.x + v.y * v.y + v.z * v.z + v.w * v.w;
        dp += v.x * w.x + v.y * w.y + v.z * w.z + v.w * w.w;
    }
#pragma unroll
    for (int o = 16; o; o >>= 1) {
        ss += __shfl_xor_sync(0xffffffffu, ss, o);
        dp += __shfl_xor_sync(0xffffffffu, dp, o);
    }
    if (lane == 0) d_logits[pid] = dp * rsqrtf(ss * (1.0f / 2048.0f) + EPSF);
}

// ---------------- K2: block0 = top-4 per batch (warp per batch); block1 = sink rows ----------------
__global__ __launch_bounds__(256) void k_topk_sink(const float* __restrict__ sink,
                                                   const float* __restrict__ tao) {
    int wid = threadIdx.x >> 5, lane = threadIdx.x & 31;
    if (blockIdx.x == 0) {
        int b = wid;
        float v[16];
#pragma unroll
        for (int i = 0; i < 16; i++) v[i] = d_logits[b * 512 + i * 32 + lane];
        int got[4];
#pragma unroll
        for (int r = 0; r < 4; r++) {
            float bv = -1e30f; int bi = 1 << 30;
#pragma unroll
            for (int i = 0; i < 16; i++) {
                int idx = i * 32 + lane;
                if (v[i] > bv || (v[i] == bv && idx < bi)) { bv = v[i]; bi = idx; }
            }
#pragma unroll
            for (int o = 16; o; o >>= 1) {
                float ov = __shfl_xor_sync(0xffffffffu, bv, o);
                int   oi = __shfl_xor_sync(0xffffffffu, bi, o);
                if (ov > bv || (ov == bv && oi < bi)) { bv = ov; bi = oi; }
            }
            got[r] = bi;
            if ((bi & 31) == lane) v[bi >> 5] = -1e30f;
        }
        if (lane == 0) {
#pragma unroll
            for (int i = 0; i < 4; i++)
#pragma unroll
                for (int j = 0; j < 3; j++)
                    if (got[j + 1] < got[j]) { int t = got[j]; got[j] = got[j + 1]; got[j + 1] = t; }
#pragma unroll
            for (int i = 0; i < 4; i++) d_topk[b * 4 + i] = got[i];
        }
    } else {
        // sink row s=0 per head (rope at s=0 is identity): Q/K = rmsnorm(sink)*tao, V = sink
        int h = wid;                              // 8 warps = 8 heads
        int c0 = lane * 4;
        float4 v = *(const float4*)(sink + h * 128 + c0);
        float ss = v.x * v.x + v.y * v.y + v.z * v.z + v.w * v.w;
#pragma unroll
        for (int o = 16; o; o >>= 1) ss += __shfl_xor_sync(0xffffffffu, ss, o);
        float n = rsqrtf(ss * (1.f / 128.f) + EPSF);
        float nq = n * tao[0], nk = n * tao[1];
        float4 q = make_float4(v.x * nq, v.y * nq, v.z * nq, v.w * nq);
        float4 k = make_float4(v.x * nk, v.y * nk, v.z * nk, v.w * nk);
#pragma unroll
        for (int b = 0; b < 8; b++) {
            size_t off = ((size_t)((b * 8 + h) * 65)) * 128 + c0;
            *(float4*)(d_Qb + off) = q;
            *(float4*)(d_Kb + off) = k;
            *(float4*)(d_Vb + off) = v;
        }
    }
}

// ---------------- K3: qkvg GEMM fused with rope+rmsnorm+tao epilogue ----------------
// grid (32 n-tiles, 8 batches), 256 threads; tile M=64 x N=128, K chunks of 32.
// nt = cb*8 + h : this block owns the full 128-channel head rows of (b, h) for
// channel-block cb — rope pairs (cc, cc+64) are lane tx <-> tx^8, rmsnorm is a
// 16-lane reduce. cat = ty&3 selects q/k/v/g and is warp-uniform.
__global__ __launch_bounds__(256) void k_qkvg(const float* __restrict__ x,
                                              const float* __restrict__ W,
                                              const float* __restrict__ cosb,
                                              const float* __restrict__ sinb,
                                              const float* __restrict__ tao) {
    int nt = blockIdx.x, b = blockIdx.y;
    int tid = threadIdx.x;
    __shared__ __align__(16) float Xs[32][68];    // [k][m]
    __shared__ __align__(16) float Ws[32][132];   // [k][n]
    __shared__ int toks[64];
    if (tid < 64) toks[tid] = d_topk[b * 4 + (tid >> 4)] * 16 + (tid & 15);
    __syncthreads();
    int tx = tid & 15, ty = tid >> 4;
    int m0 = ty * 4, n0 = tx * 8;
    ull acc[4][4];
#pragma unroll
    for (int i = 0; i < 4; i++)
#pragma unroll
        for (int j = 0; j < 4; j++) acc[i][j] = 0ull;

#pragma unroll 1
    for (int kc = 0; kc < 4; kc++) {
#pragma unroll
        for (int jj = 0; jj < 2; jj++) {
            int idx = tid + jj * 256;
            int m = idx >> 3, kq = idx & 7;
            float4 v = *(const float4*)(x + ((size_t)(b * 8192 + toks[m])) * 128 + kc * 32 + kq * 4);
            Xs[kq * 4 + 0][m] = v.x; Xs[kq * 4 + 1][m] = v.y;
            Xs[kq * 4 + 2][m] = v.z; Xs[kq * 4 + 3][m] = v.w;
        }
#pragma unroll
        for (int jj = 0; jj < 4; jj++) {
            int idx = tid + jj * 256;
            int c = idx >> 3, kq = idx & 7;
            float4 v = *(const float4*)(W + ((size_t)(nt * 128 + c)) * 128 + kc * 32 + kq * 4);
            Ws[kq * 4 + 0][c] = v.x; Ws[kq * 4 + 1][c] = v.y;
            Ws[kq * 4 + 2][c] = v.z; Ws[kq * 4 + 3][c] = v.w;
        }
        __syncthreads();
#pragma unroll
        for (int k = 0; k < 32; k++) {
            float4 xv = *(const float4*)&Xs[k][m0];
            ull xb0 = f2pk(xv.x, xv.x), xb1 = f2pk(xv.y, xv.y);
            ull xb2 = f2pk(xv.z, xv.z), xb3 = f2pk(xv.w, xv.w);
            const ull* wp = (const ull*)&Ws[k][n0];
            ull w0 = wp[0], w1 = wp[1], w2 = wp[2], w3 = wp[3];
            acc[0][0] = ffma2(xb0, w0, acc[0][0]); acc[0][1] = ffma2(xb0, w1, acc[0][1]);
            acc[0][2] = ffma2(xb0, w2, acc[0][2]); acc[0][3] = ffma2(xb0, w3, acc[0][3]);
            acc[1][0] = ffma2(xb1, w0, acc[1][0]); acc[1][1] = ffma2(xb1, w1, acc[1][1]);
            acc[1][2] = ffma2(xb1, w2, acc[1][2]); acc[1][3] = ffma2(xb1, w3, acc[1][3]);
            acc[2][0] = ffma2(xb2, w0, acc[2][0]); acc[2][1] = ffma2(xb2, w1, acc[2][1]);
            acc[2][2] = ffma2(xb2, w2, acc[2][2]); acc[2][3] = ffma2(xb2, w3, acc[2][3]);
            acc[3][0] = ffma2(xb3, w0, acc[3][0]); acc[3][1] = ffma2(xb3, w1, acc[3][1]);
            acc[3][2] = ffma2(xb3, w2, acc[3][2]); acc[3][3] = ffma2(xb3, w3, acc[3][3]);
        }
        __syncthreads();
    }

    // ---- fused epilogue ----
    int cb = nt >> 3, h = nt & 7;
    int cat = ty & 3;                             // 0=q 1=k 2=v 3=g (warp-uniform)
    int p = ty >> 2;
    int bh = b * 8 + h;
#pragma unroll
    for (int i = 0; i < 4; i++) {
        float r[8];
#pragma unroll
        for (int j = 0; j < 4; j++) {
            float2 f = f2up(acc[i][j]);
            r[2 * j] = f.x; r[2 * j + 1] = f.y;
        }
        int s0 = p * 16 + i * 4 + cb;             // row index within (b,h), 0..63
        int s = s0 + 1;
        if (cat < 2) {                            // q or k: rope + rmsnorm + tao
            float other[8];
#pragma unroll
            for (int c = 0; c < 8; c++) other[c] = __shfl_xor_sync(0xffffffffu, r[c], 8);
            int d0 = n0 & 63;
            float4 ca = *(const float4*)(cosb + s * 64 + d0);
            float4 cbv = *(const float4*)(cosb + s * 64 + d0 + 4);
            float4 sa = *(const float4*)(sinb + s * 64 + d0);
            float4 sb = *(const float4*)(sinb + s * 64 + d0 + 4);
            float cs[8] = {ca.x, ca.y, ca.z, ca.w, cbv.x, cbv.y, cbv.z, cbv.w};
            float sn[8] = {sa.x, sa.y, sa.z, sa.w, sb.x, sb.y, sb.z, sb.w};
            float sgn = (tx < 8) ? 1.f : -1.f;
            float rv[8], ssq = 0.f;
#pragma unroll
            for (int c = 0; c < 8; c++) {
                rv[c] = fmaf(r[c], cs[c], sgn * other[c] * sn[c]);
                ssq += rv[c] * rv[c];
            }
#pragma unroll
            for (int o = 8; o; o >>= 1) ssq += __shfl_xor_sync(0xffffffffu, ssq, o);
            float nrm = rsqrtf(ssq * (1.f / 128.f) + EPSF) * tao[cat];
            float* dst = (cat == 0 ? d_Qb : d_Kb) + ((size_t)bh * 65 + s) * 128 + n0;
            *(float4*)dst = make_float4(rv[0] * nrm, rv[1] * nrm, rv[2] * nrm, rv[3] * nrm);
            *(float4*)(dst + 4) = make_float4(rv[4] * nrm, rv[5] * nrm, rv[6] * nrm, rv[7] * nrm);
        } else if (cat == 2) {                    // v: raw
            float* dst = d_Vb + ((size_t)bh * 65 + s) * 128 + n0;
            *(float4*)dst = make_float4(r[0], r[1], r[2], r[3]);
            *(float4*)(dst + 4) = make_float4(r[4], r[5], r[6], r[7]);
        } else {                                  // g: raw gate logits
            float* dst = d_g + ((size_t)(b * 64 + s0)) * 1024 + h * 128 + n0;
            *(float4*)dst = make_float4(r[0], r[1], r[2], r[3]);
            *(float4*)(dst + 4) = make_float4(r[4], r[5], r[6], r[7]);
        }
    }
}

// ---------------- K5: causal attention, 2 row-chunks per (b,h), f32x2 ----------------
__global__ __launch_bounds__(256) void k_attn() {
    __shared__ __align__(16) float Ps[32 * 68];
    __shared__ __align__(16) float Buf[4224];     // Qc(32x36) + Kc(32x68); reused as Vc(32x132)
    float* Qc = Buf;
    float* Kc = Buf + 1152;
    int chunk = blockIdx.x, bh = blockIdx.y;
    int b = bh >> 3, h = bh & 7;
    int tid = threadIdx.x;
    int wid = tid >> 5, lane = tid & 31;
    const float* Qg = d_Qb + (size_t)bh * 65 * 128;
    const float* Kg = d_Kb + (size_t)bh * 65 * 128;
    const float* Vg = d_Vb + (size_t)bh * 65 * 128;
    int text = chunk ? 65 : 33;                   // t extent needed
    int r0 = wid * 4;
    int t0 = lane * 2;
    ull acc[2][2] = {0ull, 0ull, 0ull, 0ull};
    float e64 = 0.f;

#pragma unroll 1
    for (int kc = 0; kc < 4; kc++) {
        {
            int r = tid >> 3, kq = tid & 7;
            float4 qv = *(const float4*)(Qg + (size_t)(chunk * 32 + r + 1) * 128 + kc * 32 + kq * 4);
            Qc[(kq * 4 + 0) * 36 + r] = qv.x; Qc[(kq * 4 + 1) * 36 + r] = qv.y;
            Qc[(kq * 4 + 2) * 36 + r] = qv.z; Qc[(kq * 4 + 3) * 36 + r] = qv.w;
        }
        for (int idx = tid; idx < text * 8; idx += 256) {
            int t = idx >> 3, kq = idx & 7;
            float4 kv = *(const float4*)(Kg + (size_t)t * 128 + kc * 32 + kq * 4);
            Kc[(kq * 4 + 0) * 68 + t] = kv.x; Kc[(kq * 4 + 1) * 68 + t] = kv.y;
            Kc[(kq * 4 + 2) * 68 + t] = kv.z; Kc[(kq * 4 + 3) * 68 + t] = kv.w;
        }
        __syncthreads();
#pragma unroll
        for (int k = 0; k < 32; k++) {
            const ull* qp = (const ull*)&Qc[k * 36 + r0];
            ull q0 = qp[0], q1 = qp[1];
            float2 kv = *(const float2*)&Kc[k * 68 + t0];
            ull kb0 = f2pk(kv.x, kv.x), kb1 = f2pk(kv.y, kv.y);
            acc[0][0] = ffma2(q0, kb0, acc[0][0]); acc[0][1] = ffma2(q0, kb1, acc[0][1]);
            acc[1][0] = ffma2(q1, kb0, acc[1][0]); acc[1][1] = ffma2(q1, kb1, acc[1][1]);
        }
        if (chunk == 1 && tid == 0) {
#pragma unroll
            for (int k = 0; k < 32; k++) e64 += Qc[k * 36 + 31] * Kc[k * 68 + 64];
        }
        __syncthreads();
    }
    const float scl = 0.08838834764831845f;       // 1/sqrt(128)
#pragma unroll
    for (int p = 0; p < 2; p++)
#pragma unroll
        for (int j = 0; j < 2; j++) {
            float2 f = f2up(acc[p][j]);
            Ps[(r0 + 2 * p)     * 68 + t0 + j] = f.x * scl;
            Ps[(r0 + 2 * p + 1) * 68 + t0 + j] = f.y * scl;
        }
    if (chunk == 1 && tid == 0) Ps[31 * 68 + 64] = e64 * scl;
    __syncthreads();
    if (tid < 32) {
        int r = tid, s = chunk * 32 + r + 1;
        float m = -1e30f;
        for (int t = 0; t <= s; t++) m = fmaxf(m, Ps[r * 68 + t]);
        float sum = 0.f;
        for (int t = 0; t <= s; t++) { float e = __expf(Ps[r * 68 + t] - m); Ps[r * 68 + t] = e; sum += e; }
        float inv = 1.f / sum;
        for (int t = 0; t <= s; t++) Ps[r * 68 + t] *= inv;
        for (int t = s + 1; t < 65; t++) Ps[r * 68 + t] = 0.f;
    }
    __syncthreads();
    float* Vc = Buf;                              // [t][c] stride 132
    int c0 = lane * 4;
    ull y[4][2];
#pragma unroll
    for (int i = 0; i < 4; i++) { y[i][0] = 0ull; y[i][1] = 0ull; }
#pragma unroll 1
    for (int tc = 0; tc * 32 < text; tc++) {
        int tb = tc * 32;
        int tcnt = min(32, text - tb);
        for (int idx = tid; idx < tcnt * 32; idx += 256) {
            int tt = idx >> 5, kq = idx & 31;
            *(float4*)&Vc[tt * 132 + kq * 4] = *(const float4*)(Vg + (size_t)(tb + tt) * 128 + kq * 4);
        }
        __syncthreads();
        for (int tt = 0; tt < tcnt; tt++) {
            int t = tb + tt;
            float p0 = Ps[(r0 + 0) * 68 + t], p1 = Ps[(r0 + 1) * 68 + t];
            float p2 = Ps[(r0 + 2) * 68 + t], p3 = Ps[(r0 + 3) * 68 + t];
            ull pb0 = f2pk(p0, p0), pb1 = f2pk(p1, p1);
            ull pb2 = f2pk(p2, p2), pb3 = f2pk(p3, p3);
            const ull* vp = (const ull*)&Vc[tt * 132 + c0];
            ull v0 = vp[0], v1 = vp[1];
            y[0][0] = ffma2(pb0, v0, y[0][0]); y[0][1] = ffma2(pb0, v1, y[0][1]);
            y[1][0] = ffma2(pb1, v0, y[1][0]); y[1][1] = ffma2(pb1, v1, y[1][1]);
            y[2][0] = ffma2(pb2, v0, y[2][0]); y[2][1] = ffma2(pb2, v1, y[2][1]);
            y[3][0] = ffma2(pb3, v0, y[3][0]); y[3][1] = ffma2(pb3, v1, y[3][1]);
        }
        __syncthreads();
    }
#pragma unroll
    for (int i = 0; i < 4; i++) {
        int rg = chunk * 32 + r0 + i;
        const float* gb = d_g + ((size_t)(b * 64 + rg)) * 1024 + h * 128 + c0;
        float4 g4 = *(const float4*)gb;
        float2 a = f2up(y[i][0]), cpr = f2up(y[i][1]);
        float4 o;
        o.x = a.x   / (1.f + __expf(-g4.x));
        o.y = a.y   / (1.f + __expf(-g4.y));
        o.z = cpr.x / (1.f + __expf(-g4.z));
        o.w = cpr.y / (1.f + __expf(-g4.w));
        *(float4*)(d_yg + ((size_t)(b * 64 + rg)) * 1024 + h * 128 + c0) = o;
    }
}

// ---------------- K6: output GEMM, split-K=8, atomicAdd into out (f32x2) ----------------
__global__ __launch_bounds__(128) void k_out(const float* __restrict__ Wout,
                                             float* __restrict__ out) {
    int mt = blockIdx.x, nt = blockIdx.y, kc = blockIdx.z;
    __shared__ __align__(16) float Ys[32][68];
    __shared__ __align__(16) float Ws[32][68];
    int tid = threadIdx.x;
    int tx = tid & 7, ty = tid >> 3;
    int m0 = ty * 4, n0 = tx * 8;
    ull acc[4][4];
#pragma unroll
    for (int i = 0; i < 4; i++)
#pragma unroll
        for (int j = 0; j < 4; j++) acc[i][j] = 0ull;

#pragma unroll 1
    for (int ck = 0; ck < 4; ck++) {
        int kbase = kc * 128 + ck * 32;
#pragma unroll
        for (int jj = 0; jj < 4; jj++) {
            int idx = tid + jj * 128;
            int m = idx >> 3, kq = idx & 7;
            float4 v = *(const float4*)(d_yg + (size_t)(mt * 64 + m) * 1024 + kbase + kq * 4);
            Ys[kq * 4 + 0][m] = v.x; Ys[kq * 4 + 1][m] = v.y;
            Ys[kq * 4 + 2][m] = v.z; Ys[kq * 4 + 3][m] = v.w;
            float4 w = *(const float4*)(Wout + (size_t)(nt * 64 + m) * 1024 + kbase + kq * 4);
            Ws[kq * 4 + 0][m] = w.x; Ws[kq * 4 + 1][m] = w.y;
            Ws[kq * 4 + 2][m] = w.z; Ws[kq * 4 + 3][m] = w.w;
        }
        __syncthreads();
#pragma unroll
        for (int k = 0; k < 32; k++) {
            float4 yv = *(const float4*)&Ys[k][m0];
            ull yb0 = f2pk(yv.x, yv.x), yb1 = f2pk(yv.y, yv.y);
            ull yb2 = f2pk(yv.z, yv.z), yb3 = f2pk(yv.w, yv.w);
            const ull* wp = (const ull*)&Ws[k][n0];
            ull w0 = wp[0], w1 = wp[1], w2 = wp[2], w3 = wp[3];
            acc[0][0] = ffma2(yb0, w0, acc[0][0]); acc[0][1] = ffma2(yb0, w1, acc[0][1]);
            acc[0][2] = ffma2(yb0, w2, acc[0][2]); acc[0][3] = ffma2(yb0, w3, acc[0][3]);
            acc[1][0] = ffma2(yb1, w0, acc[1][0]); acc[1][1] = ffma2(yb1, w1, acc[1][1]);
            acc[1][2] = ffma2(yb1, w2, acc[1][2]); acc[1][3] = ffma2(yb1, w3, acc[1][3]);
            acc[2][0] = ffma2(yb2, w0, acc[2][0]); acc[2][1] = ffma2(yb2, w1, acc[2][1]);
            acc[2][2] = ffma2(yb2, w2, acc[2][2]); acc[2][3] = ffma2(yb2, w3, acc[2][3]);
            acc[3][0] = ffma2(yb3, w0, acc[3][0]); acc[3][1] = ffma2(yb3, w1, acc[3][1]);
            acc[3][2] = ffma2(yb3, w2, acc[3][2]); acc[3][3] = ffma2(yb3, w3, acc[3][3]);
        }
        __syncthreads();
    }
#pragma unroll
    for (int i = 0; i < 4; i++) {
        float* dst = out + (size_t)(mt * 64 + m0 + i) * 128 + nt * 64 + n0;
#pragma unroll
        for (int j = 0; j < 4; j++) {
            float2 f = f2up(acc[i][j]);
            atomicAdd(dst + 2 * j,     f.x);
            atomicAdd(dst + 2 * j + 1, f.y);
        }
    }
}

// ---------------- launch ----------------
extern "C" void kernel_launch(void* const* d_in, const int* in_sizes, int n_in,
                              void* d_out, int out_size) {
    const float* x     = (const float*)d_in[0];
    const float* cosb  = (const float*)d_in[1];
    const float* sinb  = (const float*)d_in[2];
    const float* sink  = (const float*)d_in[3];
    const float* Wqkvg = (const float*)d_in[4];
    const float* pw    = (const float*)d_in[5];
    const float* Wout  = (const float*)d_in[6];
    const float* tao   = (const float*)d_in[7];
    float* out = (float*)d_out;

    cudaMemsetAsync(out, 0, (size_t)out_size * sizeof(float));
    k_score<<<512, 256>>>(x, pw);
    k_topk_sink<<<2, 256>>>(sink, tao);
    k_qkvg<<<dim3(32, 8), 256>>>(x, Wqkvg, cosb, sinb, tao);
    k_attn<<<dim3(2, 64), 256>>>();
    k_out<<<dim3(8, 2, 8), 128>>>(Wout, out);
}